// round 10
// baseline (speedup 1.0000x reference)
#include <cuda_runtime.h>
#include <math.h>
#include <stdint.h>

#define B   8
#define H   16
#define HD  128
#define D   2048
#define NB  512
#define BS  64
#define MB  64
#define KV  (MB*BS)        // 4096
#define NCHUNK 16
#define CHUNK  (KV/NCHUNK) // 256
#define NSEG 4
#define SEG  (D/NSEG)      // 512

// ---------------- scratch (no allocations allowed) ----------------
__device__ float g_q[B*D];
__device__ float g_k[B*D];
__device__ float g_v[B*D];
__device__ float g_o[B*D];
__device__ float g_pm[B*H*NCHUNK];
__device__ float g_pl[B*H*NCHUNK];
__device__ float g_po[B*H*NCHUNK*HD];
__device__ unsigned g_cnt[B*H];            // zero-init; self-resetting
__device__ float g_part[3*NSEG*B*D];       // qkv split-k partials
__device__ float g_opart[NSEG*B*D];        // oproj split-k partials

__device__ __forceinline__ float warp_sum(float v) {
#pragma unroll
    for (int o = 16; o; o >>= 1) v += __shfl_xor_sync(0xffffffffu, v, o);
    return v;
}

// ---------------- split-K GEMV: 8 cols x 512 k per block ---------------------
// 128 threads = 4 warps, 2 cols/warp. All 8 W LDG.128 front-batched; X segment
// staged in 16KB smem. Writes raw partial dot products (bias added in combine).
__device__ __forceinline__ void gemv_splitk_body(
    const float* __restrict__ X, const float* __restrict__ W,
    float* __restrict__ part, int cblk, int seg)
{
    int tid = threadIdx.x, lane = tid & 31, w = tid >> 5;
    int c0 = cblk * 8 + w * 2;
    int k0 = seg * SEG;

    __shared__ float sX[B][SEG];
    for (int i = tid; i < B * (SEG/4); i += 128) {
        int b = i >> 7, j = i & 127;          // SEG/4 = 128
        ((float4*)sX[b])[j] = ((const float4*)(X + (size_t)b * D + k0))[j];
    }
    __syncthreads();

    // front-batch 8 independent W loads (2 cols x 4 chunks of 128 floats)
    float4 wr[2][4];
#pragma unroll
    for (int u = 0; u < 4; u++)
#pragma unroll
        for (int c = 0; c < 2; c++)
            wr[c][u] = *(const float4*)(W + (size_t)(c0 + c) * D + k0 + u * 128 + lane * 4);

    float acc[2][B];
#pragma unroll
    for (int c = 0; c < 2; c++)
#pragma unroll
        for (int b = 0; b < B; b++) acc[c][b] = 0.f;

#pragma unroll
    for (int u = 0; u < 4; u++) {
#pragma unroll
        for (int b = 0; b < B; b++) {
            float4 x4 = *(const float4*)(&sX[b][u * 128 + lane * 4]);
            acc[0][b] += wr[0][u].x*x4.x + wr[0][u].y*x4.y + wr[0][u].z*x4.z + wr[0][u].w*x4.w;
            acc[1][b] += wr[1][u].x*x4.x + wr[1][u].y*x4.y + wr[1][u].z*x4.z + wr[1][u].w*x4.w;
        }
    }

#pragma unroll
    for (int c = 0; c < 2; c++)
#pragma unroll
        for (int b = 0; b < B; b++) {
            float s = warp_sum(acc[c][b]);
            if (lane == c * 8 + b)
                part[(size_t)b * D + c0 + c] = s;
        }
}

// grid (D/8, NSEG, 3)
__global__ void __launch_bounds__(128) qkv_splitk(
    const float* __restrict__ X,
    const float* __restrict__ Wq, const float* __restrict__ Wk,
    const float* __restrict__ Wv)
{
    int mat = blockIdx.z;
    const float* W = (mat == 0) ? Wq : (mat == 1) ? Wk : Wv;
    float* part = g_part + (size_t)(mat * NSEG + blockIdx.y) * (B*D);
    gemv_splitk_body(X, W, part, blockIdx.x, blockIdx.y);
}

// grid (D/8, NSEG)
__global__ void __launch_bounds__(128) oproj_splitk(const float* __restrict__ W)
{
    float* part = g_opart + (size_t)blockIdx.y * (B*D);
    gemv_splitk_body(g_o, W, part, blockIdx.x, blockIdx.y);
}

// ---------------- combine qkv partials + bias + RoPE ------------------------
// grid B*H blocks, 64 threads; thread d handles rotary pair (d, d+64).
__global__ void __launch_bounds__(64) combine_qkv_rope(
    const float* __restrict__ bq, const float* __restrict__ bk,
    const float* __restrict__ bv, const int* __restrict__ hist)
{
    int bh = blockIdx.x;
    int b  = bh >> 4, h = bh & 15;
    int d  = threadIdx.x;                 // 0..63
    int c1 = h * HD + d;                  // col of first half
    int c2 = c1 + 64;
    size_t o1 = (size_t)b * D + c1, o2 = (size_t)b * D + c2;

    float q1 = bq[c1], q2 = bq[c2];
    float k1 = bk[c1], k2 = bk[c2];
    float v1 = bv[c1], v2 = bv[c2];
#pragma unroll
    for (int s = 0; s < NSEG; s++) {
        q1 += g_part[(size_t)(0*NSEG + s)*(B*D) + o1];
        q2 += g_part[(size_t)(0*NSEG + s)*(B*D) + o2];
        k1 += g_part[(size_t)(1*NSEG + s)*(B*D) + o1];
        k2 += g_part[(size_t)(1*NSEG + s)*(B*D) + o2];
        v1 += g_part[(size_t)(2*NSEG + s)*(B*D) + o1];
        v2 += g_part[(size_t)(2*NSEG + s)*(B*D) + o2];
    }

    int pos = hist[b];
    float inv = exp2f((float)d * -0.2076205059304601f);
    float f   = (float)pos * inv;
    float sf, cf;
    sincosf(f, &sf, &cf);

    g_q[o1] = q1*cf - q2*sf;
    g_q[o2] = q2*cf + q1*sf;
    g_k[o1] = k1*cf - k2*sf;
    g_k[o2] = k2*cf + k1*sf;
    g_v[o1] = v1;
    g_v[o2] = v2;
}

// ---------------- combine oproj partials + bias -> d_out --------------------
__global__ void __launch_bounds__(256) combine_o(
    const float* __restrict__ bo, float* __restrict__ out)
{
    int i = blockIdx.x * 256 + threadIdx.x;   // 0 .. B*D-1
    int c = i & (D - 1);
    float v = bo[c];
#pragma unroll
    for (int s = 0; s < NSEG; s++) v += g_opart[(size_t)s*(B*D) + i];
    out[i] = v;
}

// ---------------- split-KV attention partial + fused last-block combine -----
__global__ void __launch_bounds__(128) attn_partial(
    const float* __restrict__ kc, const float* __restrict__ vc,
    const int* __restrict__ hist, const int* __restrict__ bofs)
{
    int c = blockIdx.x, h = blockIdx.y, b = blockIdx.z;
    int bh = b*H + h;
    int pos = hist[b];
    int L = pos + 1;
    int s0 = c * CHUNK;
    int idx = bh*NCHUNK + c;
    int tid = threadIdx.x, lane = tid & 31, w = tid >> 5;

    bool live = (s0 < L);

    __shared__ float sm_m[4], sm_l[4];
    __shared__ float sm_o[4][HD];
    __shared__ int sblk[MB];
    __shared__ int s_last;

    if (live) {
        int s1 = min(s0 + CHUNK, L);

        if (tid < MB) sblk[tid] = bofs[b*MB + tid];
        __syncthreads();

        const float* qp   = g_q + (size_t)b*D + h*HD;
        const float* knew = g_k + (size_t)b*D + h*HD;
        const float* vnew = g_v + (size_t)b*D + h*HD;

        float4 q4 = *(const float4*)(qp + lane*4);
        const float scale = 0.08838834764831845f;  // 1/sqrt(128)

        float m = -1e30f, lacc = 0.f;
        float4 oa = make_float4(0.f, 0.f, 0.f, 0.f);

        int base = s0 + w*4;

        float4 k4[4], v4[4];
#pragma unroll
        for (int i = 0; i < 4; i++) {
            int s = min(base + i, pos);
            const float *kr, *vr;
            if (s == pos) { kr = knew; vr = vnew; }
            else {
                size_t off = (((size_t)sblk[s >> 6]*BS + (s & 63))*H + h)*(size_t)HD;
                kr = kc + off; vr = vc + off;
            }
            k4[i] = *(const float4*)(kr + lane*4);
            v4[i] = *(const float4*)(vr + lane*4);
        }

        for (; base < s1; base += 16) {
            int nbase = base + 16;
            int pbase = (nbase < s1) ? nbase : base;
            float4 kn[4], vn[4];
#pragma unroll
            for (int i = 0; i < 4; i++) {
                int s = min(pbase + i, pos);
                const float *kr, *vr;
                if (s == pos) { kr = knew; vr = vnew; }
                else {
                    size_t off = (((size_t)sblk[s >> 6]*BS + (s & 63))*H + h)*(size_t)HD;
                    kr = kc + off; vr = vc + off;
                }
                kn[i] = *(const float4*)(kr + lane*4);
                vn[i] = *(const float4*)(vr + lane*4);
            }

            float sc[4];
#pragma unroll
            for (int i = 0; i < 4; i++) {
                float dv = q4.x*k4[i].x + q4.y*k4[i].y + q4.z*k4[i].z + q4.w*k4[i].w;
                sc[i] = warp_sum(dv) * scale;
                if (base + i >= s1) sc[i] = -1e30f;
            }
            float mx = fmaxf(fmaxf(sc[0], sc[1]), fmaxf(sc[2], sc[3]));
            float mn = fmaxf(m, mx);
            float corr = __expf(m - mn);
            lacc *= corr;
            oa.x *= corr; oa.y *= corr; oa.z *= corr; oa.w *= corr;
#pragma unroll
            for (int i = 0; i < 4; i++) {
                float p = __expf(sc[i] - mn);
                lacc += p;
                oa.x += p * v4[i].x;
                oa.y += p * v4[i].y;
                oa.z += p * v4[i].z;
                oa.w += p * v4[i].w;
            }
            m = mn;

#pragma unroll
            for (int i = 0; i < 4; i++) { k4[i] = kn[i]; v4[i] = vn[i]; }
        }

        if (lane == 0) { sm_m[w] = m; sm_l[w] = lacc; }
        *(float4*)&sm_o[w][lane*4] = oa;
        __syncthreads();

        float M = fmaxf(fmaxf(sm_m[0], sm_m[1]), fmaxf(sm_m[2], sm_m[3]));
        float f0 = (sm_l[0] > 0.f) ? __expf(sm_m[0] - M) : 0.f;
        float f1 = (sm_l[1] > 0.f) ? __expf(sm_m[1] - M) : 0.f;
        float f2 = (sm_l[2] > 0.f) ? __expf(sm_m[2] - M) : 0.f;
        float f3 = (sm_l[3] > 0.f) ? __expf(sm_m[3] - M) : 0.f;

        int d = tid;
        float acc = sm_o[0][d]*f0 + sm_o[1][d]*f1 + sm_o[2][d]*f2 + sm_o[3][d]*f3;
        g_po[(size_t)idx*HD + d] = acc;
        if (tid == 0) {
            g_pm[idx] = M;
            g_pl[idx] = f0*sm_l[0] + f1*sm_l[1] + f2*sm_l[2] + f3*sm_l[3];
        }
    } else {
        if (tid == 0) { g_pm[idx] = -1e30f; g_pl[idx] = 0.f; }
    }

    // ---- arrival protocol ----
    __threadfence();
    __syncthreads();
    if (tid == 0) {
        unsigned old = atomicAdd(&g_cnt[bh], 1u);
        s_last = (old == NCHUNK - 1) ? 1 : 0;
    }
    __syncthreads();
    if (!s_last) return;

    __threadfence();

    float M = -1e30f;
#pragma unroll
    for (int cc = 0; cc < NCHUNK; cc++) M = fmaxf(M, g_pm[bh*NCHUNK + cc]);

    float Ls = 0.f;
    float4 acc = make_float4(0.f, 0.f, 0.f, 0.f);
#pragma unroll
    for (int j = 0; j < 4; j++) {
        int cc = w * 4 + j;
        float lc = g_pl[bh*NCHUNK + cc];
        float f = (lc > 0.f) ? __expf(g_pm[bh*NCHUNK + cc] - M) : 0.f;
        Ls += lc * f;
        float4 p4 = *(const float4*)(g_po + (size_t)(bh*NCHUNK + cc)*HD + lane*4);
        acc.x += p4.x * f;
        acc.y += p4.y * f;
        acc.z += p4.z * f;
        acc.w += p4.w * f;
    }

    __syncthreads();
    if (lane == 0) sm_m[w] = Ls;
    *(float4*)&sm_o[w][lane*4] = acc;
    __syncthreads();

    if (w == 0) {
        float Lt = sm_m[0] + sm_m[1] + sm_m[2] + sm_m[3];
        float inv = 1.f / Lt;
        float4 a0 = *(const float4*)&sm_o[0][lane*4];
        float4 a1 = *(const float4*)&sm_o[1][lane*4];
        float4 a2 = *(const float4*)&sm_o[2][lane*4];
        float4 a3 = *(const float4*)&sm_o[3][lane*4];
        float4 r;
        r.x = (a0.x + a1.x + a2.x + a3.x) * inv;
        r.y = (a0.y + a1.y + a2.y + a3.y) * inv;
        r.z = (a0.z + a1.z + a2.z + a3.z) * inv;
        r.w = (a0.w + a1.w + a2.w + a3.w) * inv;
        *(float4*)(g_o + (size_t)bh*HD + lane*4) = r;
        if (lane == 0) g_cnt[bh] = 0;
    }
}

// ---------------- entry point ----------------
extern "C" void kernel_launch(void* const* d_in, const int* in_sizes, int n_in,
                              void* d_out, int out_size) {
    const float* hs   = (const float*)d_in[0];
    const float* kc   = (const float*)d_in[1];
    const float* vc   = (const float*)d_in[2];
    const float* Wq   = (const float*)d_in[3];
    const float* bq   = (const float*)d_in[4];
    const float* Wk   = (const float*)d_in[5];
    const float* bk   = (const float*)d_in[6];
    const float* Wv   = (const float*)d_in[7];
    const float* bv   = (const float*)d_in[8];
    const float* Wo   = (const float*)d_in[9];
    const float* bo   = (const float*)d_in[10];
    const int*   hist = (const int*)d_in[11];
    const int*   bofs = (const int*)d_in[12];
    float* out = (float*)d_out;

    qkv_splitk<<<dim3(D/8, NSEG, 3), 128>>>(hs, Wq, Wk, Wv);         // 0
    combine_qkv_rope<<<B*H, 64>>>(bq, bk, bv, hist);                 // 1
    attn_partial<<<dim3(NCHUNK, H, B), 128>>>(kc, vc, hist, bofs);   // 2
    oproj_splitk<<<dim3(D/8, NSEG), 128>>>(Wo);                      // 3 <- profiled
    combine_o<<<(B*D)/256, 256>>>(bo, out);                          // 4
}

// round 11
// speedup vs baseline: 1.0482x; 1.0482x over previous
#include <cuda_runtime.h>
#include <math.h>
#include <stdint.h>

#define B   8
#define H   16
#define HD  128
#define D   2048
#define NB  512
#define BS  64
#define MB  64
#define KV  (MB*BS)        // 4096
#define NCHUNK 16
#define CHUNK  (KV/NCHUNK) // 256
#define NSEG 4
#define SEG  (D/NSEG)      // 512

// ---------------- scratch (no allocations allowed) ----------------
__device__ float g_q[B*D];
__device__ float g_k[B*D];
__device__ float g_v[B*D];
__device__ float g_o[B*D];
__device__ float g_pm[B*H*NCHUNK];
__device__ float g_pl[B*H*NCHUNK];
__device__ float g_po[B*H*NCHUNK*HD];
__device__ unsigned g_cnt[B*H];            // zero-init; self-resetting
__device__ float g_part[3*NSEG*B*D];       // qkv split-k partials
__device__ float g_opart[NSEG*B*D];        // oproj split-k partials

__device__ __forceinline__ float warp_sum(float v) {
#pragma unroll
    for (int o = 16; o; o >>= 1) v += __shfl_xor_sync(0xffffffffu, v, o);
    return v;
}

// ---------------- split-K GEMV v5: no smem, no sync --------------------------
// 128 threads = 4 warps, 2 cols/warp, 512-element k-segment. The 8 W LDG.128
// are issued at block start (nothing blocks them); X is read via LDG (64KB
// total -> L1/L2 resident; every warp reads the same X lines -> L1 hits).
__device__ __forceinline__ void gemv_splitk_body(
    const float* __restrict__ X, const float* __restrict__ W,
    float* __restrict__ part, int cblk, int seg)
{
    int tid = threadIdx.x, lane = tid & 31, w = tid >> 5;
    int c0 = cblk * 8 + w * 2;
    int k0 = seg * SEG;

    // front-batch 8 independent W loads (2 cols x 4 chunks of 128 floats)
    float4 wr[2][4];
#pragma unroll
    for (int u = 0; u < 4; u++)
#pragma unroll
        for (int c = 0; c < 2; c++)
            wr[c][u] = *(const float4*)(W + (size_t)(c0 + c) * D + k0 + u * 128 + lane * 4);

    float acc[2][B];
#pragma unroll
    for (int c = 0; c < 2; c++)
#pragma unroll
        for (int b = 0; b < B; b++) acc[c][b] = 0.f;

#pragma unroll
    for (int u = 0; u < 4; u++) {
#pragma unroll
        for (int b = 0; b < B; b++) {
            float4 x4 = *(const float4*)(X + (size_t)b * D + k0 + u * 128 + lane * 4);
            acc[0][b] += wr[0][u].x*x4.x + wr[0][u].y*x4.y + wr[0][u].z*x4.z + wr[0][u].w*x4.w;
            acc[1][b] += wr[1][u].x*x4.x + wr[1][u].y*x4.y + wr[1][u].z*x4.z + wr[1][u].w*x4.w;
        }
    }

#pragma unroll
    for (int c = 0; c < 2; c++)
#pragma unroll
        for (int b = 0; b < B; b++) {
            float s = warp_sum(acc[c][b]);
            if (lane == c * 8 + b)
                part[(size_t)b * D + c0 + c] = s;
        }
}

// grid (D/8, NSEG, 3)
__global__ void __launch_bounds__(128) qkv_splitk(
    const float* __restrict__ X,
    const float* __restrict__ Wq, const float* __restrict__ Wk,
    const float* __restrict__ Wv)
{
    int mat = blockIdx.z;
    const float* W = (mat == 0) ? Wq : (mat == 1) ? Wk : Wv;
    float* part = g_part + (size_t)(mat * NSEG + blockIdx.y) * (B*D);
    gemv_splitk_body(X, W, part, blockIdx.x, blockIdx.y);
}

// grid (D/8, NSEG)
__global__ void __launch_bounds__(128) oproj_splitk(const float* __restrict__ W)
{
    float* part = g_opart + (size_t)blockIdx.y * (B*D);
    gemv_splitk_body(g_o, W, part, blockIdx.x, blockIdx.y);
}

// ---------------- combine qkv partials + bias + RoPE ------------------------
__global__ void __launch_bounds__(64) combine_qkv_rope(
    const float* __restrict__ bq, const float* __restrict__ bk,
    const float* __restrict__ bv, const int* __restrict__ hist)
{
    int bh = blockIdx.x;
    int b  = bh >> 4, h = bh & 15;
    int d  = threadIdx.x;                 // 0..63
    int c1 = h * HD + d;
    int c2 = c1 + 64;
    size_t o1 = (size_t)b * D + c1, o2 = (size_t)b * D + c2;

    float q1 = bq[c1], q2 = bq[c2];
    float k1 = bk[c1], k2 = bk[c2];
    float v1 = bv[c1], v2 = bv[c2];
#pragma unroll
    for (int s = 0; s < NSEG; s++) {
        q1 += g_part[(size_t)(0*NSEG + s)*(B*D) + o1];
        q2 += g_part[(size_t)(0*NSEG + s)*(B*D) + o2];
        k1 += g_part[(size_t)(1*NSEG + s)*(B*D) + o1];
        k2 += g_part[(size_t)(1*NSEG + s)*(B*D) + o2];
        v1 += g_part[(size_t)(2*NSEG + s)*(B*D) + o1];
        v2 += g_part[(size_t)(2*NSEG + s)*(B*D) + o2];
    }

    int pos = hist[b];
    float inv = exp2f((float)d * -0.2076205059304601f);
    float f   = (float)pos * inv;
    float sf, cf;
    sincosf(f, &sf, &cf);

    g_q[o1] = q1*cf - q2*sf;
    g_q[o2] = q2*cf + q1*sf;
    g_k[o1] = k1*cf - k2*sf;
    g_k[o2] = k2*cf + k1*sf;
    g_v[o1] = v1;
    g_v[o2] = v2;
}

// ---------------- combine oproj partials + bias -> d_out --------------------
__global__ void __launch_bounds__(256) combine_o(
    const float* __restrict__ bo, float* __restrict__ out)
{
    int i = blockIdx.x * 256 + threadIdx.x;   // 0 .. B*D-1
    int c = i & (D - 1);
    float v = bo[c];
#pragma unroll
    for (int s = 0; s < NSEG; s++) v += g_opart[(size_t)s*(B*D) + i];
    out[i] = v;
}

// ---------------- split-KV attention partial + fused last-block combine -----
__global__ void __launch_bounds__(128) attn_partial(
    const float* __restrict__ kc, const float* __restrict__ vc,
    const int* __restrict__ hist, const int* __restrict__ bofs)
{
    int c = blockIdx.x, h = blockIdx.y, b = blockIdx.z;
    int bh = b*H + h;
    int pos = hist[b];
    int L = pos + 1;
    int s0 = c * CHUNK;
    int idx = bh*NCHUNK + c;
    int tid = threadIdx.x, lane = tid & 31, w = tid >> 5;

    bool live = (s0 < L);

    __shared__ float sm_m[4], sm_l[4];
    __shared__ float sm_o[4][HD];
    __shared__ int sblk[MB];
    __shared__ int s_last;

    if (live) {
        int s1 = min(s0 + CHUNK, L);

        if (tid < MB) sblk[tid] = bofs[b*MB + tid];
        __syncthreads();

        const float* qp   = g_q + (size_t)b*D + h*HD;
        const float* knew = g_k + (size_t)b*D + h*HD;
        const float* vnew = g_v + (size_t)b*D + h*HD;

        float4 q4 = *(const float4*)(qp + lane*4);
        const float scale = 0.08838834764831845f;  // 1/sqrt(128)

        float m = -1e30f, lacc = 0.f;
        float4 oa = make_float4(0.f, 0.f, 0.f, 0.f);

        int base = s0 + w*4;

        float4 k4[4], v4[4];
#pragma unroll
        for (int i = 0; i < 4; i++) {
            int s = min(base + i, pos);
            const float *kr, *vr;
            if (s == pos) { kr = knew; vr = vnew; }
            else {
                size_t off = (((size_t)sblk[s >> 6]*BS + (s & 63))*H + h)*(size_t)HD;
                kr = kc + off; vr = vc + off;
            }
            k4[i] = *(const float4*)(kr + lane*4);
            v4[i] = *(const float4*)(vr + lane*4);
        }

        for (; base < s1; base += 16) {
            int nbase = base + 16;
            int pbase = (nbase < s1) ? nbase : base;
            float4 kn[4], vn[4];
#pragma unroll
            for (int i = 0; i < 4; i++) {
                int s = min(pbase + i, pos);
                const float *kr, *vr;
                if (s == pos) { kr = knew; vr = vnew; }
                else {
                    size_t off = (((size_t)sblk[s >> 6]*BS + (s & 63))*H + h)*(size_t)HD;
                    kr = kc + off; vr = vc + off;
                }
                kn[i] = *(const float4*)(kr + lane*4);
                vn[i] = *(const float4*)(vr + lane*4);
            }

            float sc[4];
#pragma unroll
            for (int i = 0; i < 4; i++) {
                float dv = q4.x*k4[i].x + q4.y*k4[i].y + q4.z*k4[i].z + q4.w*k4[i].w;
                sc[i] = warp_sum(dv) * scale;
                if (base + i >= s1) sc[i] = -1e30f;
            }
            float mx = fmaxf(fmaxf(sc[0], sc[1]), fmaxf(sc[2], sc[3]));
            float mn = fmaxf(m, mx);
            float corr = __expf(m - mn);
            lacc *= corr;
            oa.x *= corr; oa.y *= corr; oa.z *= corr; oa.w *= corr;
#pragma unroll
            for (int i = 0; i < 4; i++) {
                float p = __expf(sc[i] - mn);
                lacc += p;
                oa.x += p * v4[i].x;
                oa.y += p * v4[i].y;
                oa.z += p * v4[i].z;
                oa.w += p * v4[i].w;
            }
            m = mn;

#pragma unroll
            for (int i = 0; i < 4; i++) { k4[i] = kn[i]; v4[i] = vn[i]; }
        }

        if (lane == 0) { sm_m[w] = m; sm_l[w] = lacc; }
        *(float4*)&sm_o[w][lane*4] = oa;
        __syncthreads();

        float M = fmaxf(fmaxf(sm_m[0], sm_m[1]), fmaxf(sm_m[2], sm_m[3]));
        float f0 = (sm_l[0] > 0.f) ? __expf(sm_m[0] - M) : 0.f;
        float f1 = (sm_l[1] > 0.f) ? __expf(sm_m[1] - M) : 0.f;
        float f2 = (sm_l[2] > 0.f) ? __expf(sm_m[2] - M) : 0.f;
        float f3 = (sm_l[3] > 0.f) ? __expf(sm_m[3] - M) : 0.f;

        int d = tid;
        float acc = sm_o[0][d]*f0 + sm_o[1][d]*f1 + sm_o[2][d]*f2 + sm_o[3][d]*f3;
        g_po[(size_t)idx*HD + d] = acc;
        if (tid == 0) {
            g_pm[idx] = M;
            g_pl[idx] = f0*sm_l[0] + f1*sm_l[1] + f2*sm_l[2] + f3*sm_l[3];
        }
    } else {
        if (tid == 0) { g_pm[idx] = -1e30f; g_pl[idx] = 0.f; }
    }

    // ---- arrival protocol ----
    __threadfence();
    __syncthreads();
    if (tid == 0) {
        unsigned old = atomicAdd(&g_cnt[bh], 1u);
        s_last = (old == NCHUNK - 1) ? 1 : 0;
    }
    __syncthreads();
    if (!s_last) return;

    __threadfence();

    float M = -1e30f;
#pragma unroll
    for (int cc = 0; cc < NCHUNK; cc++) M = fmaxf(M, g_pm[bh*NCHUNK + cc]);

    float Ls = 0.f;
    float4 acc = make_float4(0.f, 0.f, 0.f, 0.f);
#pragma unroll
    for (int j = 0; j < 4; j++) {
        int cc = w * 4 + j;
        float lc = g_pl[bh*NCHUNK + cc];
        float f = (lc > 0.f) ? __expf(g_pm[bh*NCHUNK + cc] - M) : 0.f;
        Ls += lc * f;
        float4 p4 = *(const float4*)(g_po + (size_t)(bh*NCHUNK + cc)*HD + lane*4);
        acc.x += p4.x * f;
        acc.y += p4.y * f;
        acc.z += p4.z * f;
        acc.w += p4.w * f;
    }

    __syncthreads();
    if (lane == 0) sm_m[w] = Ls;
    *(float4*)&sm_o[w][lane*4] = acc;
    __syncthreads();

    if (w == 0) {
        float Lt = sm_m[0] + sm_m[1] + sm_m[2] + sm_m[3];
        float inv = 1.f / Lt;
        float4 a0 = *(const float4*)&sm_o[0][lane*4];
        float4 a1 = *(const float4*)&sm_o[1][lane*4];
        float4 a2 = *(const float4*)&sm_o[2][lane*4];
        float4 a3 = *(const float4*)&sm_o[3][lane*4];
        float4 r;
        r.x = (a0.x + a1.x + a2.x + a3.x) * inv;
        r.y = (a0.y + a1.y + a2.y + a3.y) * inv;
        r.z = (a0.z + a1.z + a2.z + a3.z) * inv;
        r.w = (a0.w + a1.w + a2.w + a3.w) * inv;
        *(float4*)(g_o + (size_t)bh*HD + lane*4) = r;
        if (lane == 0) g_cnt[bh] = 0;
    }
}

// ---------------- entry point ----------------
extern "C" void kernel_launch(void* const* d_in, const int* in_sizes, int n_in,
                              void* d_out, int out_size) {
    const float* hs   = (const float*)d_in[0];
    const float* kc   = (const float*)d_in[1];
    const float* vc   = (const float*)d_in[2];
    const float* Wq   = (const float*)d_in[3];
    const float* bq   = (const float*)d_in[4];
    const float* Wk   = (const float*)d_in[5];
    const float* bk   = (const float*)d_in[6];
    const float* Wv   = (const float*)d_in[7];
    const float* bv   = (const float*)d_in[8];
    const float* Wo   = (const float*)d_in[9];
    const float* bo   = (const float*)d_in[10];
    const int*   hist = (const int*)d_in[11];
    const int*   bofs = (const int*)d_in[12];
    float* out = (float*)d_out;

    qkv_splitk<<<dim3(D/8, NSEG, 3), 128>>>(hs, Wq, Wk, Wv);         // 0
    combine_qkv_rope<<<B*H, 64>>>(bq, bk, bv, hist);                 // 1
    attn_partial<<<dim3(NCHUNK, H, B), 128>>>(kc, vc, hist, bofs);   // 2
    oproj_splitk<<<dim3(D/8, NSEG), 128>>>(Wo);                      // 3 <- profiled
    combine_o<<<(B*D)/256, 256>>>(bo, out);                          // 4
}